// round 7
// baseline (speedup 1.0000x reference)
#include <cuda_runtime.h>

// TripletCenterLoss — collapsed to [B x NC] distances, smem-staged f32x2 GEMM.
// B=8192, D=512, NC=55, margin=0.2. targets arrive as int32.
// R6: TM=1 (256 threads/block, 32m x 8n), 2x warp residency vs R5.

#define BB 8192
#define DD 512
#define NC 55
#define MARGINF 0.2f

#define MBLK 32          // rows per block
#define KC 32            // k-chunk (floats)
#define NCHUNK (DD / KC) // 16
#define PAD 44           // smem row stride in floats (conflict-free, 16B-aligned)

__device__ float  g_cn[56];
__device__ int    g_present[56];
__device__ float2 g_partial[256];
__device__ int    g_done = 0;

__device__ __forceinline__ void fma2(unsigned long long &d,
                                     unsigned long long a,
                                     unsigned long long b) {
    asm("fma.rn.f32x2 %0, %1, %2, %0;" : "+l"(d) : "l"(a), "l"(b));
}
__device__ __forceinline__ float lo32(unsigned long long v) {
    return __int_as_float((int)(unsigned)(v & 0xffffffffull));
}
__device__ __forceinline__ float hi32(unsigned long long v) {
    return __int_as_float((int)(unsigned)(v >> 32));
}

// ============================================================
// Prep: 56 blocks x 256 threads.
// ============================================================
__global__ void prep_kernel(const int* __restrict__ tgt,
                            const float* __restrict__ cen) {
    const int b = blockIdx.x;
    const int tid = threadIdx.x;

    if (b < NC) {
        const float2* p = (const float2*)(cen + (size_t)b * DD);
        float2 v = p[tid];
        float s = v.x * v.x + v.y * v.y;
        #pragma unroll
        for (int o = 16; o; o >>= 1) s += __shfl_xor_sync(0xffffffffu, s, o);
        __shared__ float ws[8];
        if ((tid & 31) == 0) ws[tid >> 5] = s;
        __syncthreads();
        if (tid == 0) {
            float t = 0.0f;
            #pragma unroll
            for (int w = 0; w < 8; w++) t += ws[w];
            g_cn[b] = t;
        }
    } else {
        __shared__ int flags[64];
        if (tid < 64) flags[tid] = 0;
        __syncthreads();
        #pragma unroll 8
        for (int i = tid; i < BB; i += 256) flags[tgt[i]] = 1;
        __syncthreads();
        if (tid < 56) g_present[tid] = flags[tid];
        if (tid == 0) g_cn[55] = 0.0f;
    }
}

// ============================================================
// Main: grid 256 x 256 threads. MBLK=32, TM=1, TN=7.
// thread (mt, n): mt = tid>>3 (0..31) -> row, n = tid&7 -> 7 classes.
// ============================================================
__global__ __launch_bounds__(256)
void tcl_main_kernel(const float* __restrict__ x,
                     const int* __restrict__ tgt,
                     const float* __restrict__ cen,
                     float* __restrict__ out) {
    __shared__ float xs[MBLK * PAD];   // 32 rows x 32 floats (padded)
    __shared__ float cs[56 * PAD];     // 56 classes (55 = pad, unwritten)

    const int tid = threadIdx.x;
    const int mt  = tid >> 3;          // 0..31 : my row
    const int n   = tid & 7;           // 0..7  : my class group
    const int r0  = blockIdx.x * MBLK;

    // staging map: thread -> (row = tid>>3, k4 = tid&7); exactly 256 float4
    const int srow = mt;
    const int sk4  = n;
    const float4* __restrict__ xg =
        (const float4*)(x + (size_t)(r0 + srow) * DD) + sk4;

    // compute-phase smem pointers (16B aligned: PAD*4 = 176)
    const ulonglong2* __restrict__ aptr = (const ulonglong2*)(xs + mt * PAD);
    int cls[7];
    const ulonglong2* __restrict__ bptr[7];
    #pragma unroll
    for (int j = 0; j < 7; j++) {
        cls[j] = n * 7 + j;
        bptr[j] = (const ulonglong2*)(cs + cls[j] * PAD);
    }

    unsigned long long acc[7], xn2;
    xn2 = 0ull;
    #pragma unroll
    for (int j = 0; j < 7; j++) acc[j] = 0ull;

    // prefetch registers
    float4 px, pc[2];

    // ---- prefetch chunk 0 ----
    px = __ldg(xg);
    #pragma unroll
    for (int q = 0; q < 2; q++) {
        int idx = tid + q * 256;
        if (idx < 440) {
            int cl = idx >> 3, k4 = idx & 7;
            pc[q] = __ldg((const float4*)(cen + (size_t)cl * DD) + k4);
        }
    }

    #pragma unroll 1
    for (int c = 0; c < NCHUNK; c++) {
        __syncthreads();   // prior compute done -> safe to overwrite smem
        *(float4*)(xs + srow * PAD + sk4 * 4) = px;
        #pragma unroll
        for (int q = 0; q < 2; q++) {
            int idx = tid + q * 256;
            if (idx < 440)
                *(float4*)(cs + (idx >> 3) * PAD + (idx & 7) * 4) = pc[q];
        }
        __syncthreads();

        // prefetch next chunk (overlaps with compute below)
        if (c + 1 < NCHUNK) {
            px = __ldg(xg + (c + 1) * 8);
            #pragma unroll
            for (int q = 0; q < 2; q++) {
                int idx = tid + q * 256;
                if (idx < 440) {
                    int cl = idx >> 3, k4 = idx & 7;
                    pc[q] = __ldg((const float4*)(cen + (size_t)cl * DD)
                                  + (c + 1) * 8 + k4);
                }
            }
        }

        // compute: 8 k4-steps from smem
        #pragma unroll
        for (int k4 = 0; k4 < 8; k4++) {
            ulonglong2 a = aptr[k4];
            fma2(xn2, a.x, a.x);
            fma2(xn2, a.y, a.y);
            #pragma unroll
            for (int j = 0; j < 7; j++) {
                ulonglong2 b = bptr[j][k4];
                fma2(acc[j], a.x, b.x);
                fma2(acc[j], a.y, b.y);
            }
        }
    }

    // ---- epilogue ----
    float lsum = 0.0f, psum = 0.0f;
    {
        float xn = lo32(xn2) + hi32(xn2);
        int tg = tgt[r0 + mt];
        float ap = -1e30f, an = 1e30f;
        #pragma unroll
        for (int j = 0; j < 7; j++) {
            if (cls[j] >= NC || !g_present[cls[j]]) continue;
            float S = lo32(acc[j]) + hi32(acc[j]);
            float d2 = xn + g_cn[cls[j]] - 2.0f * S;
            float d = sqrtf(fmaxf(d2, 1e-12f));
            if (cls[j] == tg) ap = d;
            else an = fminf(an, d);
        }
        // combine across the 8 n-lanes of this row (contiguous lanes)
        #pragma unroll
        for (int o = 1; o < 8; o <<= 1) {
            ap = fmaxf(ap, __shfl_xor_sync(0xffffffffu, ap, o));
            an = fminf(an, __shfl_xor_sync(0xffffffffu, an, o));
        }
        if (n == 0) {
            lsum = fmaxf(ap - an + MARGINF, 0.0f);
            psum = (an > ap) ? 1.0f : 0.0f;
        }
    }
    // warp sum (non n==0 lanes hold 0)
    #pragma unroll
    for (int o = 16; o; o >>= 1) {
        lsum += __shfl_xor_sync(0xffffffffu, lsum, o);
        psum += __shfl_xor_sync(0xffffffffu, psum, o);
    }

    __shared__ float2 red[8];
    if ((tid & 31) == 0) red[tid >> 5] = make_float2(lsum, psum);
    __syncthreads();

    __shared__ int lastflag;
    if (tid == 0) {
        float a = 0.0f, b = 0.0f;
        #pragma unroll
        for (int w = 0; w < 8; w++) { a += red[w].x; b += red[w].y; }
        g_partial[blockIdx.x] = make_float2(a, b);
        __threadfence();
        int old = atomicAdd(&g_done, 1);
        lastflag = (old == (int)gridDim.x - 1) ? 1 : 0;
    }
    __syncthreads();

    if (lastflag) {
        __shared__ float2 s[256];
        s[tid] = g_partial[tid];
        __syncthreads();
        #pragma unroll
        for (int o = 128; o; o >>= 1) {
            if (tid < o) { s[tid].x += s[tid + o].x; s[tid].y += s[tid + o].y; }
            __syncthreads();
        }
        if (tid == 0) {
            out[0] = s[0].x / (float)BB;
            out[1] = s[0].y / (float)BB;
            g_done = 0;   // reset for graph replay
        }
    }
}

extern "C" void kernel_launch(void* const* d_in, const int* in_sizes, int n_in,
                              void* d_out, int out_size) {
    const float* x   = (const float*)d_in[0];
    const int*   tgt = (const int*)d_in[1];
    const float* cen = (const float*)d_in[2];
    float* out = (float*)d_out;

    prep_kernel<<<56, 256>>>(tgt, cen);
    tcl_main_kernel<<<256, 256>>>(x, tgt, cen, out);
}

// round 8
// speedup vs baseline: 1.4487x; 1.4487x over previous
#include <cuda_runtime.h>

// TripletCenterLoss — collapsed to [B x NC] distances, smem-staged f32x2 GEMM.
// B=8192, D=512, NC=55, margin=0.2. targets arrive as int32.
// R7: TM=2 + K-split-2 (256 thr: 2 halves x 16m x 8n), MBLK=32, grid 256.
//     Keeps R5's LDS:FMA ratio with 2x the warp residency.

#define BB 8192
#define DD 512
#define NC 55
#define MARGINF 0.2f

#define MBLK 32            // rows per block
#define KCH 64             // K-floats staged per chunk (16 float4)
#define NCHUNK (DD / KCH)  // 8
#define PAD 76             // smem row stride in floats (conflict-free, 16B-aligned)

__device__ float  g_cn[56];
__device__ int    g_present[56];
__device__ float2 g_partial[256];
__device__ int    g_done = 0;

__device__ __forceinline__ void fma2(unsigned long long &d,
                                     unsigned long long a,
                                     unsigned long long b) {
    asm("fma.rn.f32x2 %0, %1, %2, %0;" : "+l"(d) : "l"(a), "l"(b));
}
__device__ __forceinline__ void add2(unsigned long long &d,
                                     unsigned long long a) {
    asm("add.rn.f32x2 %0, %0, %1;" : "+l"(d) : "l"(a));
}
__device__ __forceinline__ float lo32(unsigned long long v) {
    return __int_as_float((int)(unsigned)(v & 0xffffffffull));
}
__device__ __forceinline__ float hi32(unsigned long long v) {
    return __int_as_float((int)(unsigned)(v >> 32));
}

// ============================================================
// Prep: 56 blocks x 256 threads.
// ============================================================
__global__ void prep_kernel(const int* __restrict__ tgt,
                            const float* __restrict__ cen) {
    const int b = blockIdx.x;
    const int tid = threadIdx.x;

    if (b < NC) {
        const float2* p = (const float2*)(cen + (size_t)b * DD);
        float2 v = p[tid];
        float s = v.x * v.x + v.y * v.y;
        #pragma unroll
        for (int o = 16; o; o >>= 1) s += __shfl_xor_sync(0xffffffffu, s, o);
        __shared__ float ws[8];
        if ((tid & 31) == 0) ws[tid >> 5] = s;
        __syncthreads();
        if (tid == 0) {
            float t = 0.0f;
            #pragma unroll
            for (int w = 0; w < 8; w++) t += ws[w];
            g_cn[b] = t;
        }
    } else {
        __shared__ int flags[64];
        if (tid < 64) flags[tid] = 0;
        __syncthreads();
        #pragma unroll 8
        for (int i = tid; i < BB; i += 256) flags[tgt[i]] = 1;
        __syncthreads();
        if (tid < 56) g_present[tid] = flags[tid];
        if (tid == 0) g_cn[55] = 0.0f;
    }
}

// ============================================================
// Main: grid 256 x 256 threads.
// ============================================================
__global__ __launch_bounds__(256)
void tcl_main_kernel(const float* __restrict__ x,
                     const int* __restrict__ tgt,
                     const float* __restrict__ cen,
                     float* __restrict__ out) {
    __shared__ float xs[MBLK * PAD];              // 32 rows x 64 floats (padded)
    __shared__ float cs[56 * PAD];                // 56 classes (55 = pad)
    __shared__ unsigned long long comb[16][128];  // half-1 partials

    const int tid = threadIdx.x;
    const int h   = tid >> 7;          // K-half 0/1
    const int t   = tid & 127;
    const int mt  = t >> 3;            // 0..15 : row pair
    const int n   = t & 7;             // 0..7  : class group
    const int r0  = blockIdx.x * MBLK;

    // ---- staging maps ----
    // X: 512 float4 slots (32 rows x 16 k4) -> 2 per thread
    const float4* __restrict__ xg[2];
    int xo[2];
    #pragma unroll
    for (int q = 0; q < 2; q++) {
        int idx = tid + q * 256;
        int row = idx >> 4, k4 = idx & 15;
        xg[q] = (const float4*)(x + (size_t)(r0 + row) * DD) + k4;
        xo[q] = row * PAD + k4 * 4;
    }
    // C: 880 float4 slots (55 classes x 16 k4) -> up to 4 per thread
    const float4* __restrict__ cg[4];
    int co[4];
    #pragma unroll
    for (int q = 0; q < 4; q++) {
        int idx = tid + q * 256;
        if (idx < 880) {
            int cl = idx >> 4, k4 = idx & 15;
            cg[q] = (const float4*)(cen + (size_t)cl * DD) + k4;
            co[q] = cl * PAD + k4 * 4;
        } else { cg[q] = 0; co[q] = 0; }
    }

    // ---- compute-phase smem pointers ----
    const ulonglong2* __restrict__ aptr[2];
    #pragma unroll
    for (int i = 0; i < 2; i++)
        aptr[i] = (const ulonglong2*)(xs + (mt * 2 + i) * PAD) + h * 8;
    int cls[7];
    const ulonglong2* __restrict__ bptr[7];
    #pragma unroll
    for (int j = 0; j < 7; j++) {
        cls[j] = n * 7 + j;
        bptr[j] = (const ulonglong2*)(cs + cls[j] * PAD) + h * 8;
    }

    unsigned long long acc[2][7], xn2[2];
    #pragma unroll
    for (int i = 0; i < 2; i++) {
        xn2[i] = 0ull;
        #pragma unroll
        for (int j = 0; j < 7; j++) acc[i][j] = 0ull;
    }

    // ---- prefetch chunk 0 ----
    float4 px[2], pc[4];
    #pragma unroll
    for (int q = 0; q < 2; q++) px[q] = __ldg(xg[q]);
    #pragma unroll
    for (int q = 0; q < 4; q++) if (cg[q]) pc[q] = __ldg(cg[q]);

    #pragma unroll 1
    for (int c = 0; c < NCHUNK; c++) {
        __syncthreads();
        #pragma unroll
        for (int q = 0; q < 2; q++) *(float4*)(xs + xo[q]) = px[q];
        #pragma unroll
        for (int q = 0; q < 4; q++) if (cg[q]) *(float4*)(cs + co[q]) = pc[q];
        __syncthreads();

        if (c + 1 < NCHUNK) {
            #pragma unroll
            for (int q = 0; q < 2; q++) px[q] = __ldg(xg[q] + (c + 1) * 16);
            #pragma unroll
            for (int q = 0; q < 4; q++)
                if (cg[q]) pc[q] = __ldg(cg[q] + (c + 1) * 16);
        }

        // 8 k4-steps from my K-half of the chunk
        #pragma unroll
        for (int k4 = 0; k4 < 8; k4++) {
            ulonglong2 b[7];
            #pragma unroll
            for (int j = 0; j < 7; j++) b[j] = bptr[j][k4];
            #pragma unroll
            for (int i = 0; i < 2; i++) {
                ulonglong2 a = aptr[i][k4];
                fma2(xn2[i], a.x, a.x);
                fma2(xn2[i], a.y, a.y);
                #pragma unroll
                for (int j = 0; j < 7; j++) {
                    fma2(acc[i][j], a.x, b[j].x);
                    fma2(acc[i][j], a.y, b[j].y);
                }
            }
        }
    }

    // ---- combine K-halves ----
    __syncthreads();   // compute done in both halves before reuse pattern
    if (h == 1) {
        #pragma unroll
        for (int i = 0; i < 2; i++) {
            #pragma unroll
            for (int j = 0; j < 7; j++) comb[i * 7 + j][t] = acc[i][j];
            comb[14 + i][t] = xn2[i];
        }
    }
    __syncthreads();

    __shared__ float2 red[4];
    if (h == 0) {
        #pragma unroll
        for (int i = 0; i < 2; i++) {
            #pragma unroll
            for (int j = 0; j < 7; j++) add2(acc[i][j], comb[i * 7 + j][t]);
            add2(xn2[i], comb[14 + i][t]);
        }

        // ---- epilogue ----
        float lsum = 0.0f, psum = 0.0f;
        #pragma unroll
        for (int i = 0; i < 2; i++) {
            float xn = lo32(xn2[i]) + hi32(xn2[i]);
            int tg = tgt[r0 + mt * 2 + i];
            float ap = -1e30f, an = 1e30f;
            #pragma unroll
            for (int j = 0; j < 7; j++) {
                if (cls[j] >= NC || !g_present[cls[j]]) continue;
                float S = lo32(acc[i][j]) + hi32(acc[i][j]);
                float d2 = xn + g_cn[cls[j]] - 2.0f * S;
                float d = sqrtf(fmaxf(d2, 1e-12f));
                if (cls[j] == tg) ap = d;
                else an = fminf(an, d);
            }
            #pragma unroll
            for (int o = 1; o < 8; o <<= 1) {
                ap = fmaxf(ap, __shfl_xor_sync(0xffffffffu, ap, o));
                an = fminf(an, __shfl_xor_sync(0xffffffffu, an, o));
            }
            if (n == 0) {
                lsum += fmaxf(ap - an + MARGINF, 0.0f);
                psum += (an > ap) ? 1.0f : 0.0f;
            }
        }
        #pragma unroll
        for (int o = 16; o; o >>= 1) {
            lsum += __shfl_xor_sync(0xffffffffu, lsum, o);
            psum += __shfl_xor_sync(0xffffffffu, psum, o);
        }
        if ((t & 31) == 0) red[t >> 5] = make_float2(lsum, psum);
    }
    __syncthreads();

    // ---- publish block partial + last-block finalize ----
    __shared__ int lastflag;
    if (tid == 0) {
        float a = 0.0f, b = 0.0f;
        #pragma unroll
        for (int w = 0; w < 4; w++) { a += red[w].x; b += red[w].y; }
        g_partial[blockIdx.x] = make_float2(a, b);
        __threadfence();
        int old = atomicAdd(&g_done, 1);
        lastflag = (old == (int)gridDim.x - 1) ? 1 : 0;
    }
    __syncthreads();

    if (lastflag) {
        __shared__ float2 s[256];
        s[tid] = g_partial[tid];
        __syncthreads();
        #pragma unroll
        for (int o = 128; o; o >>= 1) {
            if (tid < o) { s[tid].x += s[tid + o].x; s[tid].y += s[tid + o].y; }
            __syncthreads();
        }
        if (tid == 0) {
            out[0] = s[0].x / (float)BB;
            out[1] = s[0].y / (float)BB;
            g_done = 0;   // reset for graph replay
        }
    }
}

extern "C" void kernel_launch(void* const* d_in, const int* in_sizes, int n_in,
                              void* d_out, int out_size) {
    const float* x   = (const float*)d_in[0];
    const int*   tgt = (const int*)d_in[1];
    const float* cen = (const float*)d_in[2];
    float* out = (float*)d_out;

    prep_kernel<<<56, 256>>>(tgt, cen);
    tcl_main_kernel<<<256, 256>>>(x, tgt, cen, out);
}

// round 10
// speedup vs baseline: 2.2523x; 1.5547x over previous
#include <cuda_runtime.h>
#include <cstdint>

// TripletCenterLoss via warp-level mma.sync (tf32) — sm_100-base-safe.
// B=8192, D=512, NC=55, margin=0.2. targets int32.
// CTA: 256 thr = 2 M-warps x 4 K-quarters, MTILE=32, grid 256.

#define BB 8192
#define DD 512
#define NC 55
#define MARGINF 0.2f

#define MTILE 32
#define GRID_MAIN (BB / MTILE)   // 256
#define KCH 64                   // floats per staged chunk
#define NCHUNK (DD / KCH)        // 8
#define PAD 68                   // smem floats per row (bank-conflict-free)

__device__ float  g_cn[56];
__device__ int    g_present[56];
__device__ float2 g_partial[GRID_MAIN];
__device__ int    g_done = 0;

__device__ __forceinline__ uint32_t f2tf(float f) {
    uint32_t r;
    asm("cvt.rna.tf32.f32 %0, %1;" : "=r"(r) : "f"(f));
    return r;
}
__device__ __forceinline__ void mma_tf32(float* d, uint32_t a0, uint32_t a1,
                                         uint32_t a2, uint32_t a3,
                                         uint32_t b0, uint32_t b1) {
    asm volatile(
        "mma.sync.aligned.m16n8k8.row.col.f32.tf32.tf32.f32 "
        "{%0,%1,%2,%3}, {%4,%5,%6,%7}, {%8,%9}, {%0,%1,%2,%3};"
        : "+f"(d[0]), "+f"(d[1]), "+f"(d[2]), "+f"(d[3])
        : "r"(a0), "r"(a1), "r"(a2), "r"(a3), "r"(b0), "r"(b1));
}

// ============================================================
// Prep: 56 blocks x 256 threads (fp32 center norms + present)
// ============================================================
__global__ void prep_kernel(const int* __restrict__ tgt,
                            const float* __restrict__ cen) {
    const int b = blockIdx.x;
    const int tid = threadIdx.x;
    if (b < NC) {
        const float2* p = (const float2*)(cen + (size_t)b * DD);
        float2 v = p[tid];
        float s = v.x * v.x + v.y * v.y;
        #pragma unroll
        for (int o = 16; o; o >>= 1) s += __shfl_xor_sync(0xffffffffu, s, o);
        __shared__ float ws[8];
        if ((tid & 31) == 0) ws[tid >> 5] = s;
        __syncthreads();
        if (tid == 0) {
            float t = 0.0f;
            #pragma unroll
            for (int w = 0; w < 8; w++) t += ws[w];
            g_cn[b] = t;
        }
    } else {
        __shared__ int flags[64];
        if (tid < 64) flags[tid] = 0;
        __syncthreads();
        #pragma unroll 8
        for (int i = tid; i < BB; i += 256) flags[tgt[i]] = 1;
        __syncthreads();
        if (tid < 56) g_present[tid] = flags[tid];
        if (tid == 0) g_cn[55] = 0.0f;
    }
}

// ============================================================
// Main kernel
// ============================================================
__global__ __launch_bounds__(256, 2)
void tcl_mma_kernel(const float* __restrict__ x,
                    const int* __restrict__ tgt,
                    const float* __restrict__ cen,
                    float* __restrict__ out) {
    __shared__ __align__(16) uint32_t As[MTILE * PAD];  // tf32 X tile
    __shared__ __align__(16) uint32_t Bs[56 * PAD];     // tf32 C tile
    __shared__ __align__(16) float comb[6 * 7 * 128];   // K-quarters 1..3 D frags
    __shared__ float  xn[MTILE];
    __shared__ float2 red[2];

    const int tid  = threadIdx.x;
    const int w    = tid >> 5;
    const int lane = tid & 31;
    const int wm   = w & 1;          // M-half (16 rows)
    const int kq   = w >> 1;         // K-quarter (0..3)
    const int g    = lane >> 2;      // fragment group row
    const int q4   = lane & 3;       // fragment group col
    const int r0   = blockIdx.x * MTILE;

    // ---- staging maps ----
    // A: 512 float4/chunk; thread -> row=tid>>3, 2 slots q*8+(tid&7)
    const int arow = tid >> 3, acol = tid & 7;
    const float4* __restrict__ xg = (const float4*)(x + (size_t)(r0 + arow) * DD);
    // B: 896 float4/chunk; idx = tid + q*256 -> row=idx>>4, slot=idx&15
    const float4* __restrict__ bgp[4];
    int brow[4], bsl[4], bval[4], bzero[4];
    #pragma unroll
    for (int q = 0; q < 4; q++) {
        int idx = tid + q * 256;
        bval[q]  = idx < 896;
        brow[q]  = idx >> 4;
        bsl[q]   = idx & 15;
        bzero[q] = brow[q] >= NC;
        int lr = (brow[q] < NC) ? brow[q] : NC - 1;
        bgp[q] = (const float4*)(cen + (size_t)lr * DD);
    }

    // ---- accumulators ----
    float d[7][4];
    #pragma unroll
    for (int j = 0; j < 7; j++) {
        d[j][0] = d[j][1] = d[j][2] = d[j][3] = 0.0f;
    }
    float nacc = 0.0f;

    // ---- prefetch chunk 0 ----
    float4 pa[2], pb[4];
    #pragma unroll
    for (int q = 0; q < 2; q++) pa[q] = __ldg(xg + q * 8 + acol);
    #pragma unroll
    for (int q = 0; q < 4; q++)
        pb[q] = (bval[q] && !bzero[q]) ? __ldg(bgp[q] + bsl[q])
                                       : make_float4(0.f, 0.f, 0.f, 0.f);

    const uint32_t* __restrict__ aF0 = As + (wm * 16 + g) * PAD;       // rows g
    const uint32_t* __restrict__ aF1 = aF0 + 8 * PAD;                  // rows g+8

    #pragma unroll 1
    for (int c = 0; c < NCHUNK; c++) {
        __syncthreads();
        // store (cvt to tf32) + exact-fp32 norm accumulation
        #pragma unroll
        for (int q = 0; q < 2; q++) {
            float4 v = pa[q];
            nacc += v.x * v.x + v.y * v.y + v.z * v.z + v.w * v.w;
            uint32_t* p = As + arow * PAD + (q * 8 + acol) * 4;
            p[0] = f2tf(v.x); p[1] = f2tf(v.y); p[2] = f2tf(v.z); p[3] = f2tf(v.w);
        }
        #pragma unroll
        for (int q = 0; q < 4; q++) {
            if (!bval[q]) continue;
            float4 v = pb[q];
            uint32_t* p = Bs + brow[q] * PAD + bsl[q] * 4;
            p[0] = f2tf(v.x); p[1] = f2tf(v.y); p[2] = f2tf(v.z); p[3] = f2tf(v.w);
        }
        __syncthreads();

        if (c + 1 < NCHUNK) {
            #pragma unroll
            for (int q = 0; q < 2; q++)
                pa[q] = __ldg(xg + (c + 1) * 16 + q * 8 + acol);
            #pragma unroll
            for (int q = 0; q < 4; q++)
                if (bval[q] && !bzero[q])
                    pb[q] = __ldg(bgp[q] + (c + 1) * 16 + bsl[q]);
        }

        // my K-quarter: 2 k8-steps of this chunk
        #pragma unroll
        for (int s = 0; s < 2; s++) {
            const int k0 = (kq * 2 + s) * 8 + q4;
            uint32_t a0 = aF0[k0],     a1 = aF1[k0];
            uint32_t a2 = aF0[k0 + 4], a3 = aF1[k0 + 4];
            #pragma unroll
            for (int j = 0; j < 7; j++) {
                const uint32_t* bb = Bs + (j * 8 + g) * PAD;
                mma_tf32(d[j], a0, a1, a2, a3, bb[k0], bb[k0 + 4]);
            }
        }
    }

    // ---- row norms (8 threads per row) ----
    #pragma unroll
    for (int o = 1; o < 8; o <<= 1) nacc += __shfl_xor_sync(0xffffffffu, nacc, o);
    if ((tid & 7) == 0) xn[arow] = nacc;

    // ---- combine K-quarters ----
    if (kq > 0) {
        #pragma unroll
        for (int j = 0; j < 7; j++) {
            float4* p = (float4*)(comb + ((((kq - 1) * 2 + wm) * 7 + j) * 128
                                          + lane * 4));
            *p = make_float4(d[j][0], d[j][1], d[j][2], d[j][3]);
        }
    }
    __syncthreads();

    if (kq == 0) {
        #pragma unroll
        for (int r = 0; r < 3; r++) {
            #pragma unroll
            for (int j = 0; j < 7; j++) {
                float4 v = *(const float4*)(comb + (((r * 2 + wm) * 7 + j) * 128
                                                    + lane * 4));
                d[j][0] += v.x; d[j][1] += v.y; d[j][2] += v.z; d[j][3] += v.w;
            }
        }

        // ---- epilogue: rows rA = wm*16+g, rB = rA+8 ----
        float lsum = 0.0f, psum = 0.0f;
        #pragma unroll
        for (int half = 0; half < 2; half++) {
            const int lrow = wm * 16 + g + half * 8;
            const float xnv = xn[lrow];
            const int   tg  = tgt[r0 + lrow];
            float ap = -1e30f, an = 1e30f;
            #pragma unroll
            for (int j = 0; j < 7; j++) {
                #pragma unroll
                for (int e = 0; e < 2; e++) {
                    int n = j * 8 + 2 * q4 + e;
                    if (n >= NC || !g_present[n]) continue;
                    float S = d[j][half * 2 + e];
                    float d2 = xnv + g_cn[n] - 2.0f * S;
                    float dd = sqrtf(fmaxf(d2, 1e-12f));
                    if (n == tg) ap = dd;
                    else an = fminf(an, dd);
                }
            }
            // reduce over the 4 lanes of this fragment group
            #pragma unroll
            for (int o = 1; o < 4; o <<= 1) {
                ap = fmaxf(ap, __shfl_xor_sync(0xffffffffu, ap, o));
                an = fminf(an, __shfl_xor_sync(0xffffffffu, an, o));
            }
            if (q4 == 0) {
                lsum += fmaxf(ap - an + MARGINF, 0.0f);
                psum += (an > ap) ? 1.0f : 0.0f;
            }
        }
        #pragma unroll
        for (int o = 16; o; o >>= 1) {
            lsum += __shfl_xor_sync(0xffffffffu, lsum, o);
            psum += __shfl_xor_sync(0xffffffffu, psum, o);
        }
        if (lane == 0) red[wm] = make_float2(lsum, psum);
    }
    __syncthreads();

    // ---- publish partial + last-block finalize ----
    __shared__ int lastflag;
    if (tid == 0) {
        g_partial[blockIdx.x] = make_float2(red[0].x + red[1].x,
                                            red[0].y + red[1].y);
        __threadfence();
        int old = atomicAdd(&g_done, 1);
        lastflag = (old == GRID_MAIN - 1) ? 1 : 0;
    }
    __syncthreads();

    if (lastflag) {
        __shared__ float2 s[256];
        s[tid] = g_partial[tid];
        __syncthreads();
        #pragma unroll
        for (int o = 128; o; o >>= 1) {
            if (tid < o) { s[tid].x += s[tid + o].x; s[tid].y += s[tid + o].y; }
            __syncthreads();
        }
        if (tid == 0) {
            out[0] = s[0].x / (float)BB;
            out[1] = s[0].y / (float)BB;
            g_done = 0;   // reset for graph replay
        }
    }
}

extern "C" void kernel_launch(void* const* d_in, const int* in_sizes, int n_in,
                              void* d_out, int out_size) {
    const float* x   = (const float*)d_in[0];
    const int*   tgt = (const int*)d_in[1];
    const float* cen = (const float*)d_in[2];
    float* out = (float*)d_out;

    prep_kernel<<<56, 256>>>(tgt, cen);
    tcl_mma_kernel<<<GRID_MAIN, 256>>>(x, tgt, cen, out);
}

// round 11
// speedup vs baseline: 2.2557x; 1.0015x over previous
#include <cuda_runtime.h>
#include <cstdint>

// TripletCenterLoss via warp-level mma.sync (tf32), cp.async double-buffered.
// B=8192, D=512, NC=55, margin=0.2. targets int32.
// CTA: 256 thr = 2 M-warps x 4 K-quarters, MTILE=32, grid 256.
// Raw fp32 bits fed to tf32 MMA (HW truncation); norms exact fp32 from smem.

#define BB 8192
#define DD 512
#define NC 55
#define MARGINF 0.2f

#define MTILE 32
#define GRID_MAIN (BB / MTILE)   // 256
#define KCH 64                   // floats per staged chunk
#define NCHUNK (DD / KCH)        // 8
#define PAD 68                   // smem floats per row (conflict-free, 16B rows)
#define ROWS_TOT 88              // 32 A-rows + 56 B-rows
#define BUFSZ (ROWS_TOT * PAD)   // floats per buffer

__device__ float  g_cn[56];
__device__ int    g_present[56];
__device__ float2 g_partial[GRID_MAIN];
__device__ int    g_done = 0;

__device__ __forceinline__ uint32_t smem_u32(const void* p) {
    uint32_t a;
    asm("{ .reg .u64 t; cvta.to.shared.u64 t, %1; cvt.u32.u64 %0, t; }"
        : "=r"(a) : "l"(p));
    return a;
}
__device__ __forceinline__ void cpa16(uint32_t dst, const void* src) {
    asm volatile("cp.async.cg.shared.global [%0], [%1], 16;"
                 :: "r"(dst), "l"(src));
}
#define CP_COMMIT() asm volatile("cp.async.commit_group;" ::: "memory")
#define CP_WAIT(n)  asm volatile("cp.async.wait_group %0;" :: "n"(n) : "memory")

__device__ __forceinline__ void mma_tf32(float* d, uint32_t a0, uint32_t a1,
                                         uint32_t a2, uint32_t a3,
                                         uint32_t b0, uint32_t b1) {
    asm volatile(
        "mma.sync.aligned.m16n8k8.row.col.f32.tf32.tf32.f32 "
        "{%0,%1,%2,%3}, {%4,%5,%6,%7}, {%8,%9}, {%0,%1,%2,%3};"
        : "+f"(d[0]), "+f"(d[1]), "+f"(d[2]), "+f"(d[3])
        : "r"(a0), "r"(a1), "r"(a2), "r"(a3), "r"(b0), "r"(b1));
}

// ============================================================
// Prep: 56 blocks x 256 threads (fp32 center norms + present)
// ============================================================
__global__ void prep_kernel(const int* __restrict__ tgt,
                            const float* __restrict__ cen) {
    const int b = blockIdx.x;
    const int tid = threadIdx.x;
    if (b < NC) {
        const float2* p = (const float2*)(cen + (size_t)b * DD);
        float2 v = p[tid];
        float s = v.x * v.x + v.y * v.y;
        #pragma unroll
        for (int o = 16; o; o >>= 1) s += __shfl_xor_sync(0xffffffffu, s, o);
        __shared__ float ws[8];
        if ((tid & 31) == 0) ws[tid >> 5] = s;
        __syncthreads();
        if (tid == 0) {
            float t = 0.0f;
            #pragma unroll
            for (int w = 0; w < 8; w++) t += ws[w];
            g_cn[b] = t;
        }
    } else {
        __shared__ int flags[64];
        if (tid < 64) flags[tid] = 0;
        __syncthreads();
        #pragma unroll 8
        for (int i = tid; i < BB; i += 256) flags[tgt[i]] = 1;
        __syncthreads();
        if (tid < 56) g_present[tid] = flags[tid];
        if (tid == 0) g_cn[55] = 0.0f;
    }
}

// ============================================================
// Main kernel
// ============================================================
__global__ __launch_bounds__(256, 2)
void tcl_mma_kernel(const float* __restrict__ x,
                    const int* __restrict__ tgt,
                    const float* __restrict__ cen,
                    float* __restrict__ out) {
    // double-buffered staging pool (aliased later by combine + finalize scratch)
    __shared__ __align__(16) float pool[2 * BUFSZ];   // 47872 B
    __shared__ float  xn[MTILE];
    __shared__ float2 red[2];

    const int tid  = threadIdx.x;
    const int w    = tid >> 5;
    const int lane = tid & 31;
    const int wm   = w & 1;          // M-half (16 rows)
    const int kq   = w >> 1;         // K-quarter (0..3)
    const int g    = lane >> 2;      // fragment group row
    const int q4   = lane & 3;       // fragment group col
    const int r0   = blockIdx.x * MTILE;

    const uint32_t pool_sa = smem_u32(pool);

    // ---- staging maps (16B slots) ----
    // A: 512 slots/chunk: idx = tid + q*256 -> row = idx>>4 (0..31), slot = idx&15
    const int arow0 = tid >> 4;            // q=0 row
    const int aslot = tid & 15;
    const float4* __restrict__ xg0 =
        (const float4*)(x + (size_t)(r0 + arow0) * DD) + aslot;
    const float4* __restrict__ xg1 =
        (const float4*)(x + (size_t)(r0 + arow0 + 16) * DD) + aslot;
    const uint32_t adst0 = (uint32_t)((arow0 * PAD + aslot * 4) * 4);
    const uint32_t adst1 = (uint32_t)(((arow0 + 16) * PAD + aslot * 4) * 4);
    // B: 880 valid slots/chunk (55 rows x 16): idx = tid + q*256
    const float4* __restrict__ bgp[4];
    uint32_t bdst[4];
    int bok[4];
    #pragma unroll
    for (int q = 0; q < 4; q++) {
        int idx = tid + q * 256;
        int brow = idx >> 4, bslot = idx & 15;
        bok[q] = (idx < 880);
        int lr = brow < NC ? brow : NC - 1;
        bgp[q]  = (const float4*)(cen + (size_t)lr * DD) + bslot;
        bdst[q] = (uint32_t)(((32 + brow) * PAD + bslot * 4) * 4);
    }

    // zero B pad row (row 55) in both buffers — never overwritten afterwards
    if (tid < 32) {
        int buf = tid >> 4, sl = tid & 15;
        *(float4*)(pool + buf * BUFSZ + (32 + 55) * PAD + sl * 4) =
            make_float4(0.f, 0.f, 0.f, 0.f);
    }

    // ---- accumulators ----
    float d[7][4];
    #pragma unroll
    for (int j = 0; j < 7; j++)
        d[j][0] = d[j][1] = d[j][2] = d[j][3] = 0.0f;
    float na0 = 0.0f, na1 = 0.0f;

    // ---- issue chunk 0 ----
    {
        const uint32_t bb = pool_sa;
        cpa16(bb + adst0, xg0);
        cpa16(bb + adst1, xg1);
        #pragma unroll
        for (int q = 0; q < 4; q++)
            if (bok[q]) cpa16(bb + bdst[q], bgp[q]);
        CP_COMMIT();
    }

    #pragma unroll 1
    for (int c = 0; c < NCHUNK; c++) {
        const int buf = c & 1;
        if (c + 1 < NCHUNK) {
            const uint32_t bb = pool_sa + (uint32_t)((buf ^ 1) * BUFSZ * 4);
            const int ofs = (c + 1) * 16;        // float4 step per chunk
            cpa16(bb + adst0, xg0 + ofs);
            cpa16(bb + adst1, xg1 + ofs);
            #pragma unroll
            for (int q = 0; q < 4; q++)
                if (bok[q]) cpa16(bb + bdst[q], bgp[q] + ofs);
            CP_COMMIT();
            CP_WAIT(1);
        } else {
            CP_WAIT(0);
        }
        __syncthreads();

        const float* As = pool + buf * BUFSZ;
        const float* Bs = As + 32 * PAD;

        // exact-fp32 row-norm accumulation from staged data
        {
            float4 v0 = *(const float4*)(As + arow0 * PAD + aslot * 4);
            float4 v1 = *(const float4*)(As + (arow0 + 16) * PAD + aslot * 4);
            na0 += v0.x * v0.x + v0.y * v0.y + v0.z * v0.z + v0.w * v0.w;
            na1 += v1.x * v1.x + v1.y * v1.y + v1.z * v1.z + v1.w * v1.w;
        }

        const uint32_t* aF0 = (const uint32_t*)(As + (wm * 16 + g) * PAD);
        const uint32_t* aF1 = aF0 + 8 * PAD;

        // my K-quarter: 2 k8-steps of this chunk
        #pragma unroll
        for (int s = 0; s < 2; s++) {
            const int k0 = (kq * 2 + s) * 8 + q4;
            uint32_t a0 = aF0[k0],     a1 = aF1[k0];
            uint32_t a2 = aF0[k0 + 4], a3 = aF1[k0 + 4];
            #pragma unroll
            for (int j = 0; j < 7; j++) {
                const uint32_t* bb2 = (const uint32_t*)(Bs + (j * 8 + g) * PAD);
                mma_tf32(d[j], a0, a1, a2, a3, bb2[k0], bb2[k0 + 4]);
            }
        }
        __syncthreads();   // all compute on buf done before it is re-issued
    }

    // ---- row norms: reduce over 16 staging lanes per row ----
    #pragma unroll
    for (int o = 1; o < 16; o <<= 1) {
        na0 += __shfl_xor_sync(0xffffffffu, na0, o);
        na1 += __shfl_xor_sync(0xffffffffu, na1, o);
    }
    if ((tid & 15) == 0) {
        xn[arow0] = na0;
        xn[arow0 + 16] = na1;
    }

    // ---- combine K-quarters (comb aliases the staging pool) ----
    float* comb = pool;                       // 5376 floats needed, pool has 11968
    if (kq > 0) {
        #pragma unroll
        for (int j = 0; j < 7; j++) {
            float4* p = (float4*)(comb + ((((kq - 1) * 2 + wm) * 7 + j) * 128
                                          + lane * 4));
            *p = make_float4(d[j][0], d[j][1], d[j][2], d[j][3]);
        }
    }
    __syncthreads();

    if (kq == 0) {
        #pragma unroll
        for (int r = 0; r < 3; r++) {
            #pragma unroll
            for (int j = 0; j < 7; j++) {
                float4 v = *(const float4*)(comb + (((r * 2 + wm) * 7 + j) * 128
                                                    + lane * 4));
                d[j][0] += v.x; d[j][1] += v.y; d[j][2] += v.z; d[j][3] += v.w;
            }
        }

        // ---- epilogue: rows wm*16+g and +8 ----
        float lsum = 0.0f, psum = 0.0f;
        #pragma unroll
        for (int half = 0; half < 2; half++) {
            const int lrow = wm * 16 + g + half * 8;
            const float xnv = xn[lrow];
            const int   tg  = tgt[r0 + lrow];
            float ap = -1e30f, an = 1e30f;
            #pragma unroll
            for (int j = 0; j < 7; j++) {
                #pragma unroll
                for (int e = 0; e < 2; e++) {
                    int n = j * 8 + 2 * q4 + e;
                    if (n >= NC || !g_present[n]) continue;
                    float S = d[j][half * 2 + e];
                    float d2 = xnv + g_cn[n] - 2.0f * S;
                    float dd = sqrtf(fmaxf(d2, 1e-12f));
                    if (n == tg) ap = dd;
                    else an = fminf(an, dd);
                }
            }
            #pragma unroll
            for (int o = 1; o < 4; o <<= 1) {
                ap = fmaxf(ap, __shfl_xor_sync(0xffffffffu, ap, o));
                an = fminf(an, __shfl_xor_sync(0xffffffffu, an, o));
            }
            if (q4 == 0) {
                lsum += fmaxf(ap - an + MARGINF, 0.0f);
                psum += (an > ap) ? 1.0f : 0.0f;
            }
        }
        #pragma unroll
        for (int o = 16; o; o >>= 1) {
            lsum += __shfl_xor_sync(0xffffffffu, lsum, o);
            psum += __shfl_xor_sync(0xffffffffu, psum, o);
        }
        if (lane == 0) red[wm] = make_float2(lsum, psum);
    }
    __syncthreads();

    // ---- publish partial + last-block finalize ----
    __shared__ int lastflag;
    if (tid == 0) {
        g_partial[blockIdx.x] = make_float2(red[0].x + red[1].x,
                                            red[0].y + red[1].y);
        __threadfence();
        int old = atomicAdd(&g_done, 1);
        lastflag = (old == GRID_MAIN - 1) ? 1 : 0;
    }
    __syncthreads();

    if (lastflag) {
        float2* fs = (float2*)(pool + 6144);   // finalize scratch, aliases pool
        fs[tid] = g_partial[tid];
        __syncthreads();
        #pragma unroll
        for (int o = 128; o; o >>= 1) {
            if (tid < o) { fs[tid].x += fs[tid + o].x; fs[tid].y += fs[tid + o].y; }
            __syncthreads();
        }
        if (tid == 0) {
            out[0] = fs[0].x / (float)BB;
            out[1] = fs[0].y / (float)BB;
            g_done = 0;   // reset for graph replay
        }
    }
}

extern "C" void kernel_launch(void* const* d_in, const int* in_sizes, int n_in,
                              void* d_out, int out_size) {
    const float* x   = (const float*)d_in[0];
    const int*   tgt = (const int*)d_in[1];
    const float* cen = (const float*)d_in[2];
    float* out = (float*)d_out;

    prep_kernel<<<56, 256>>>(tgt, cen);
    tcl_mma_kernel<<<GRID_MAIN, 256>>>(x, tgt, cen, out);
}

// round 12
// speedup vs baseline: 2.2977x; 1.0186x over previous
#include <cuda_runtime.h>
#include <cstdint>

// TripletCenterLoss via warp-level mma.sync (tf32), 3-stage cp.async pipeline.
// B=8192, D=512, NC=55, margin=0.2. targets int32.
// CTA: 256 thr = 2 M-warps x 4 K-quarters, MTILE=32, grid 256.
// Centers pre-rounded to tf32 values (prep); A fragments cvt.rna in registers.

#define BB 8192
#define DD 512
#define NC 55
#define MARGINF 0.2f

#define MTILE 32
#define GRID_MAIN (BB / MTILE)   // 256
#define CHK 32                   // K-floats per chunk
#define NCH (DD / CHK)           // 16
#define NSTG 3                   // pipeline stages
#define PADF 36                  // floats per smem row (conflict-free, 16B mult)
#define AROWS 32
#define BROWS 56
#define STGF ((AROWS + BROWS) * PADF)   // 3168 floats per stage

__device__ float  g_cn[56];
__device__ int    g_present[56];
__device__ float  g_ctf[56 * DD];     // centers rounded to tf32 values
__device__ float2 g_partial[GRID_MAIN];
__device__ int    g_done = 0;

__device__ __forceinline__ uint32_t smem_u32(const void* p) {
    uint32_t a;
    asm("{ .reg .u64 t; cvta.to.shared.u64 t, %1; cvt.u32.u64 %0, t; }"
        : "=r"(a) : "l"(p));
    return a;
}
__device__ __forceinline__ void cpa16(uint32_t dst, const void* src) {
    asm volatile("cp.async.cg.shared.global [%0], [%1], 16;"
                 :: "r"(dst), "l"(src));
}
#define CP_COMMIT() asm volatile("cp.async.commit_group;" ::: "memory")
#define CP_WAIT(n)  asm volatile("cp.async.wait_group %0;" :: "n"(n) : "memory")

__device__ __forceinline__ uint32_t f2tf(float f) {
    uint32_t r;
    asm("cvt.rna.tf32.f32 %0, %1;" : "=r"(r) : "f"(f));
    return r;
}
__device__ __forceinline__ void mma_tf32(float* d, uint32_t a0, uint32_t a1,
                                         uint32_t a2, uint32_t a3,
                                         uint32_t b0, uint32_t b1) {
    asm volatile(
        "mma.sync.aligned.m16n8k8.row.col.f32.tf32.tf32.f32 "
        "{%0,%1,%2,%3}, {%4,%5,%6,%7}, {%8,%9}, {%0,%1,%2,%3};"
        : "+f"(d[0]), "+f"(d[1]), "+f"(d[2]), "+f"(d[3])
        : "r"(a0), "r"(a1), "r"(a2), "r"(a3), "r"(b0), "r"(b1));
}

// ============================================================
// Prep: 56 blocks x 256 threads.
// b < NC: center norm (exact) + tf32-rounded copy. b == NC: present flags.
// ============================================================
__global__ void prep_kernel(const int* __restrict__ tgt,
                            const float* __restrict__ cen) {
    const int b = blockIdx.x;
    const int tid = threadIdx.x;
    if (b < NC) {
        const float2* p = (const float2*)(cen + (size_t)b * DD);
        float2 v = p[tid];
        float s = v.x * v.x + v.y * v.y;
        g_ctf[b * DD + tid * 2 + 0] = __uint_as_float(f2tf(v.x));
        g_ctf[b * DD + tid * 2 + 1] = __uint_as_float(f2tf(v.y));
        #pragma unroll
        for (int o = 16; o; o >>= 1) s += __shfl_xor_sync(0xffffffffu, s, o);
        __shared__ float ws[8];
        if ((tid & 31) == 0) ws[tid >> 5] = s;
        __syncthreads();
        if (tid == 0) {
            float t = 0.0f;
            #pragma unroll
            for (int w = 0; w < 8; w++) t += ws[w];
            g_cn[b] = t;
        }
    } else {
        __shared__ int flags[64];
        if (tid < 64) flags[tid] = 0;
        __syncthreads();
        #pragma unroll 8
        for (int i = tid; i < BB; i += 256) flags[tgt[i]] = 1;
        __syncthreads();
        if (tid < 56) g_present[tid] = flags[tid];
        if (tid == 0) g_cn[55] = 0.0f;
    }
}

// ============================================================
// Main kernel
// ============================================================
__global__ __launch_bounds__(256, 2)
void tcl_mma_kernel(const float* __restrict__ x,
                    const int* __restrict__ tgt,
                    float* __restrict__ out) {
    __shared__ __align__(16) float pool[NSTG * STGF];   // 38016 B
    __shared__ float  xn[MTILE];
    __shared__ float2 red[2];

    const int tid  = threadIdx.x;
    const int w    = tid >> 5;
    const int lane = tid & 31;
    const int wm   = w & 1;          // M-half (16 rows)
    const int kq   = w >> 1;         // K-quarter (0..3)
    const int g    = lane >> 2;      // fragment group row
    const int q4   = lane & 3;       // fragment group col
    const int r0   = blockIdx.x * MTILE;

    const uint32_t pool_sa = smem_u32(pool);

    // ---- staging maps (float4 slots, per chunk) ----
    // A: 256 slots: row = tid>>3 (0..31), sl = tid&7
    const int arow = tid >> 3, asl = tid & 7;
    const float4* __restrict__ xg =
        (const float4*)(x + (size_t)(r0 + arow) * DD) + asl;
    const uint32_t adst = (uint32_t)((arow * PADF + asl * 4) * 4);
    // B: 440 slots (55 rows x 8): idx = tid + q*256
    const float4* __restrict__ bgp[2];
    uint32_t bdst[2];
    int bok[2];
    #pragma unroll
    for (int q = 0; q < 2; q++) {
        int idx = tid + q * 256;
        int brow = idx >> 3, bsl = idx & 7;
        bok[q] = (idx < 440);
        int lr = brow < NC ? brow : NC - 1;
        bgp[q]  = (const float4*)(g_ctf + (size_t)lr * DD) + bsl;
        bdst[q] = (uint32_t)(((AROWS + brow) * PADF + bsl * 4) * 4);
    }

    // zero B pad row (row 55) in all stages — never overwritten afterwards
    if (tid < NSTG * 8) {
        int st = tid >> 3, sl = tid & 7;
        *(float4*)(pool + st * STGF + (AROWS + 55) * PADF + sl * 4) =
            make_float4(0.f, 0.f, 0.f, 0.f);
    }

    // ---- accumulators ----
    float d[7][4];
    #pragma unroll
    for (int j = 0; j < 7; j++)
        d[j][0] = d[j][1] = d[j][2] = d[j][3] = 0.0f;
    float na = 0.0f;

    // ---- prologue: issue chunks 0, 1 ----
    #pragma unroll
    for (int c = 0; c < NSTG - 1; c++) {
        const uint32_t bb = pool_sa + (uint32_t)(c * STGF * 4);
        cpa16(bb + adst, xg + c * 8);
        #pragma unroll
        for (int q = 0; q < 2; q++)
            if (bok[q]) cpa16(bb + bdst[q], bgp[q] + c * 8);
        CP_COMMIT();
    }

    int buf = 0;
    #pragma unroll 1
    for (int c = 0; c < NCH; c++) {
        CP_WAIT(NSTG - 2);       // chunk c landed
        __syncthreads();         // all warps done with buf (c-1)%NSTG, data visible

        // issue chunk c+2 into buf (c+2)%NSTG (== (c-1)%NSTG, freed by the bar)
        if (c + NSTG - 1 < NCH) {
            int nb = buf + (NSTG - 1);
            if (nb >= NSTG) nb -= NSTG;
            const uint32_t bb = pool_sa + (uint32_t)(nb * STGF * 4);
            const int ofs = (c + NSTG - 1) * 8;
            cpa16(bb + adst, xg + ofs);
            #pragma unroll
            for (int q = 0; q < 2; q++)
                if (bok[q]) cpa16(bb + bdst[q], bgp[q] + ofs);
        }
        CP_COMMIT();             // empty groups at tail keep the count aligned

        const float* As = pool + buf * STGF;
        const float* Bs = As + AROWS * PADF;

        // exact row-norm accumulation (raw fp32 X from smem)
        {
            float4 v = *(const float4*)(As + arow * PADF + asl * 4);
            na += v.x * v.x + v.y * v.y + v.z * v.z + v.w * v.w;
        }

        // my K-quarter: 1 k8-step of this chunk
        {
            const int k0 = kq * 8 + q4;
            const uint32_t* aF0 = (const uint32_t*)(As + (wm * 16 + g) * PADF);
            const uint32_t* aF1 = aF0 + 8 * PADF;
            uint32_t a0 = f2tf(__uint_as_float(aF0[k0]));
            uint32_t a1 = f2tf(__uint_as_float(aF1[k0]));
            uint32_t a2 = f2tf(__uint_as_float(aF0[k0 + 4]));
            uint32_t a3 = f2tf(__uint_as_float(aF1[k0 + 4]));
            #pragma unroll
            for (int j = 0; j < 7; j++) {
                const uint32_t* bb2 = (const uint32_t*)(Bs + (j * 8 + g) * PADF);
                mma_tf32(d[j], a0, a1, a2, a3, bb2[k0], bb2[k0 + 4]);
            }
        }

        if (++buf == NSTG) buf = 0;
    }

    // ---- row norms: reduce over the 8 staging lanes of each row ----
    #pragma unroll
    for (int o = 1; o < 8; o <<= 1) na += __shfl_xor_sync(0xffffffffu, na, o);
    if ((tid & 7) == 0) xn[arow] = na;

    __syncthreads();   // pool free for reuse as combine scratch

    // ---- combine K-quarters (comb aliases the staging pool) ----
    float* comb = pool;                      // needs 5376 floats, pool has 9504
    if (kq > 0) {
        #pragma unroll
        for (int j = 0; j < 7; j++) {
            float4* p = (float4*)(comb + ((((kq - 1) * 2 + wm) * 7 + j) * 128
                                          + lane * 4));
            *p = make_float4(d[j][0], d[j][1], d[j][2], d[j][3]);
        }
    }
    __syncthreads();

    if (kq == 0) {
        #pragma unroll
        for (int r = 0; r < 3; r++) {
            #pragma unroll
            for (int j = 0; j < 7; j++) {
                float4 v = *(const float4*)(comb + (((r * 2 + wm) * 7 + j) * 128
                                                    + lane * 4));
                d[j][0] += v.x; d[j][1] += v.y; d[j][2] += v.z; d[j][3] += v.w;
            }
        }

        // ---- epilogue: rows wm*16+g and +8 ----
        float lsum = 0.0f, psum = 0.0f;
        #pragma unroll
        for (int half = 0; half < 2; half++) {
            const int lrow = wm * 16 + g + half * 8;
            const float xnv = xn[lrow];
            const int   tg  = tgt[r0 + lrow];
            float ap = -1e30f, an = 1e30f;
            #pragma unroll
            for (int j = 0; j < 7; j++) {
                #pragma unroll
                for (int e = 0; e < 2; e++) {
                    int n = j * 8 + 2 * q4 + e;
                    if (n >= NC || !g_present[n]) continue;
                    float S = d[j][half * 2 + e];
                    float d2 = xnv + g_cn[n] - 2.0f * S;
                    float dd = sqrtf(fmaxf(d2, 1e-12f));
                    if (n == tg) ap = dd;
                    else an = fminf(an, dd);
                }
            }
            #pragma unroll
            for (int o = 1; o < 4; o <<= 1) {
                ap = fmaxf(ap, __shfl_xor_sync(0xffffffffu, ap, o));
                an = fminf(an, __shfl_xor_sync(0xffffffffu, an, o));
            }
            if (q4 == 0) {
                lsum += fmaxf(ap - an + MARGINF, 0.0f);
                psum += (an > ap) ? 1.0f : 0.0f;
            }
        }
        #pragma unroll
        for (int o = 16; o; o >>= 1) {
            lsum += __shfl_xor_sync(0xffffffffu, lsum, o);
            psum += __shfl_xor_sync(0xffffffffu, psum, o);
        }
        if (lane == 0) red[wm] = make_float2(lsum, psum);
    }
    __syncthreads();

    // ---- publish partial + last-block finalize ----
    __shared__ int lastflag;
    if (tid == 0) {
        g_partial[blockIdx.x] = make_float2(red[0].x + red[1].x,
                                            red[0].y + red[1].y);
        __threadfence();
        int old = atomicAdd(&g_done, 1);
        lastflag = (old == GRID_MAIN - 1) ? 1 : 0;
    }
    __syncthreads();

    if (lastflag) {
        float2* fs = (float2*)(pool + 6144);   // finalize scratch aliases pool
        fs[tid] = g_partial[tid];
        __syncthreads();
        #pragma unroll
        for (int o = 128; o; o >>= 1) {
            if (tid < o) { fs[tid].x += fs[tid + o].x; fs[tid].y += fs[tid + o].y; }
            __syncthreads();
        }
        if (tid == 0) {
            out[0] = fs[0].x / (float)BB;
            out[1] = fs[0].y / (float)BB;
            g_done = 0;   // reset for graph replay
        }
    }
}

extern "C" void kernel_launch(void* const* d_in, const int* in_sizes, int n_in,
                              void* d_out, int out_size) {
    const float* x   = (const float*)d_in[0];
    const int*   tgt = (const int*)d_in[1];
    const float* cen = (const float*)d_in[2];
    float* out = (float*)d_out;

    prep_kernel<<<56, 256>>>(tgt, cen);
    tcl_mma_kernel<<<GRID_MAIN, 256>>>(x, tgt, out);
}

// round 13
// speedup vs baseline: 2.4577x; 1.0697x over previous
#include <cuda_runtime.h>
#include <cstdint>

// TripletCenterLoss — single fused kernel. mma.sync tf32, 3-stage cp.async.
// B=8192, D=512, NC=55, margin=0.2. targets int32.
// CTA: 256 thr = 2 M-warps x 4 K-quarters, MTILE=32, grid 256.
// Per-CTA: present-flags from full tgt scan; exact center norms from staged B;
// rna rounding of A and B fragments in registers.

#define BB 8192
#define DD 512
#define NC 55
#define MARGINF 0.2f

#define MTILE 32
#define GRID_MAIN (BB / MTILE)   // 256
#define CHK 32                   // K-floats per chunk
#define NCH (DD / CHK)           // 16
#define NSTG 3                   // pipeline stages
#define PADF 36                  // floats per smem row (conflict-free, 16B mult)
#define AROWS 32
#define BROWS 56
#define STGF ((AROWS + BROWS) * PADF)   // 3168 floats per stage

__device__ float2 g_partial[GRID_MAIN];
__device__ int    g_done = 0;

__device__ __forceinline__ uint32_t smem_u32(const void* p) {
    uint32_t a;
    asm("{ .reg .u64 t; cvta.to.shared.u64 t, %1; cvt.u32.u64 %0, t; }"
        : "=r"(a) : "l"(p));
    return a;
}
__device__ __forceinline__ void cpa16(uint32_t dst, const void* src) {
    asm volatile("cp.async.cg.shared.global [%0], [%1], 16;"
                 :: "r"(dst), "l"(src));
}
#define CP_COMMIT() asm volatile("cp.async.commit_group;" ::: "memory")
#define CP_WAIT(n)  asm volatile("cp.async.wait_group %0;" :: "n"(n) : "memory")

__device__ __forceinline__ uint32_t f2tf(float f) {
    uint32_t r;
    asm("cvt.rna.tf32.f32 %0, %1;" : "=r"(r) : "f"(f));
    return r;
}
__device__ __forceinline__ void mma_tf32(float* d, uint32_t a0, uint32_t a1,
                                         uint32_t a2, uint32_t a3,
                                         uint32_t b0, uint32_t b1) {
    asm volatile(
        "mma.sync.aligned.m16n8k8.row.col.f32.tf32.tf32.f32 "
        "{%0,%1,%2,%3}, {%4,%5,%6,%7}, {%8,%9}, {%0,%1,%2,%3};"
        : "+f"(d[0]), "+f"(d[1]), "+f"(d[2]), "+f"(d[3])
        : "r"(a0), "r"(a1), "r"(a2), "r"(a3), "r"(b0), "r"(b1));
}

// ============================================================
// Fused main kernel
// ============================================================
__global__ __launch_bounds__(256, 2)
void tcl_mma_kernel(const float* __restrict__ x,
                    const int* __restrict__ tgt,
                    const float* __restrict__ cen,
                    float* __restrict__ out) {
    __shared__ __align__(16) float pool[NSTG * STGF];   // 38016 B
    __shared__ float  xn[MTILE];
    __shared__ float  scn[56];       // exact center norms (computed in-CTA)
    __shared__ int    sflags[56];    // class-present flags (computed in-CTA)
    __shared__ float2 red[2];

    const int tid  = threadIdx.x;
    const int w    = tid >> 5;
    const int lane = tid & 31;
    const int wm   = w & 1;          // M-half (16 rows)
    const int kq   = w >> 1;         // K-quarter (0..3)
    const int g    = lane >> 2;      // fragment group row
    const int q4   = lane & 3;       // fragment group col
    const int r0   = blockIdx.x * MTILE;

    const uint32_t pool_sa = smem_u32(pool);

    // ---- staging maps (float4 slots, per chunk) ----
    // A: 256 slots: row = tid>>3 (0..31), sl = tid&7
    const int arow = tid >> 3, asl = tid & 7;
    const float4* __restrict__ xg =
        (const float4*)(x + (size_t)(r0 + arow) * DD) + asl;
    const uint32_t adst = (uint32_t)((arow * PADF + asl * 4) * 4);
    // B: 440 valid slots (55 rows x 8): idx = tid + q*256
    const float4* __restrict__ bgp[2];
    uint32_t bdst[2];
    int bok[2], browq[2];
    #pragma unroll
    for (int q = 0; q < 2; q++) {
        int idx = tid + q * 256;
        int brow = idx >> 3, bsl = idx & 7;
        bok[q]   = (idx < 440);
        browq[q] = brow;
        int lr = brow < NC ? brow : NC - 1;
        bgp[q]  = (const float4*)(cen + (size_t)lr * DD) + bsl;
        bdst[q] = (uint32_t)(((AROWS + brow) * PADF + bsl * 4) * 4);
    }

    // zero B pad row (row 55) in all stages — never overwritten afterwards
    if (tid < NSTG * 8) {
        int st = tid >> 3, sl = tid & 7;
        *(float4*)(pool + st * STGF + (AROWS + 55) * PADF + sl * 4) =
            make_float4(0.f, 0.f, 0.f, 0.f);
    }

    // ---- prologue: issue chunks 0, 1 ----
    #pragma unroll
    for (int c = 0; c < NSTG - 1; c++) {
        const uint32_t bb = pool_sa + (uint32_t)(c * STGF * 4);
        cpa16(bb + adst, xg + c * 8);
        #pragma unroll
        for (int q = 0; q < 2; q++)
            if (bok[q]) cpa16(bb + bdst[q], bgp[q] + c * 8);
        CP_COMMIT();
    }

    // ---- present flags: full tgt scan (overlaps the cp.async prologue) ----
    if (tid < 56) sflags[tid] = 0;
    __syncthreads();
    {
        const int4* tg4 = (const int4*)tgt;
        #pragma unroll
        for (int q = 0; q < 8; q++) {
            int4 v = __ldg(tg4 + tid + q * 256);
            sflags[v.x] = 1; sflags[v.y] = 1;
            sflags[v.z] = 1; sflags[v.w] = 1;
        }
    }

    // ---- accumulators ----
    float d[7][4];
    #pragma unroll
    for (int j = 0; j < 7; j++)
        d[j][0] = d[j][1] = d[j][2] = d[j][3] = 0.0f;
    float na = 0.0f;            // A row-norm partial
    float nb[2] = {0.f, 0.f};   // B row-norm partials (exact, raw staged data)

    int buf = 0;
    #pragma unroll 1
    for (int c = 0; c < NCH; c++) {
        CP_WAIT(NSTG - 2);       // chunk c landed
        __syncthreads();         // all warps done with buf (c-1)%NSTG, data visible

        // issue chunk c+2 into buf (c+2)%NSTG (freed by the bar above)
        if (c + NSTG - 1 < NCH) {
            int nbuf = buf + (NSTG - 1);
            if (nbuf >= NSTG) nbuf -= NSTG;
            const uint32_t bb = pool_sa + (uint32_t)(nbuf * STGF * 4);
            const int ofs = (c + NSTG - 1) * 8;
            cpa16(bb + adst, xg + ofs);
            #pragma unroll
            for (int q = 0; q < 2; q++)
                if (bok[q]) cpa16(bb + bdst[q], bgp[q] + ofs);
        }
        CP_COMMIT();             // empty groups at tail keep the count aligned

        const float* As = pool + buf * STGF;
        const float* Bs = As + AROWS * PADF;

        // exact norm accumulation from raw staged data
        {
            float4 v = *(const float4*)(As + arow * PADF + asl * 4);
            na += v.x * v.x + v.y * v.y + v.z * v.z + v.w * v.w;
            #pragma unroll
            for (int q = 0; q < 2; q++) {
                if (!bok[q]) continue;
                float4 b = *(const float4*)((const float*)pool + buf * STGF
                                            + (bdst[q] >> 2));
                nb[q] += b.x * b.x + b.y * b.y + b.z * b.z + b.w * b.w;
            }
        }

        // my K-quarter: 1 k8-step of this chunk (rna in registers, A and B)
        {
            const int k0 = kq * 8 + q4;
            const uint32_t* aF0 = (const uint32_t*)(As + (wm * 16 + g) * PADF);
            const uint32_t* aF1 = aF0 + 8 * PADF;
            uint32_t a0 = f2tf(__uint_as_float(aF0[k0]));
            uint32_t a1 = f2tf(__uint_as_float(aF1[k0]));
            uint32_t a2 = f2tf(__uint_as_float(aF0[k0 + 4]));
            uint32_t a3 = f2tf(__uint_as_float(aF1[k0 + 4]));
            #pragma unroll
            for (int j = 0; j < 7; j++) {
                const uint32_t* bb2 = (const uint32_t*)(Bs + (j * 8 + g) * PADF);
                uint32_t b0 = f2tf(__uint_as_float(bb2[k0]));
                uint32_t b1 = f2tf(__uint_as_float(bb2[k0 + 4]));
                mma_tf32(d[j], a0, a1, a2, a3, b0, b1);
            }
        }

        if (++buf == NSTG) buf = 0;
    }

    // ---- A row norms: reduce over the 8 staging lanes of each row ----
    #pragma unroll
    for (int o = 1; o < 8; o <<= 1) na += __shfl_xor_sync(0xffffffffu, na, o);
    if ((tid & 7) == 0) xn[arow] = na;

    // ---- B row norms: 8 consecutive lanes share a row ----
    #pragma unroll
    for (int q = 0; q < 2; q++) {
        #pragma unroll
        for (int o = 1; o < 8; o <<= 1)
            nb[q] += __shfl_xor_sync(0xffffffffu, nb[q], o);
        if (bok[q] && (tid & 7) == 0) scn[browq[q]] = nb[q];
    }

    __syncthreads();   // pool free for reuse; xn/scn/sflags complete

    // ---- combine K-quarters (comb aliases the staging pool) ----
    float* comb = pool;                      // needs 5376 floats, pool has 9504
    if (kq > 0) {
        #pragma unroll
        for (int j = 0; j < 7; j++) {
            float4* p = (float4*)(comb + ((((kq - 1) * 2 + wm) * 7 + j) * 128
                                          + lane * 4));
            *p = make_float4(d[j][0], d[j][1], d[j][2], d[j][3]);
        }
    }
    __syncthreads();

    if (kq == 0) {
        #pragma unroll
        for (int r = 0; r < 3; r++) {
            #pragma unroll
            for (int j = 0; j < 7; j++) {
                float4 v = *(const float4*)(comb + (((r * 2 + wm) * 7 + j) * 128
                                                    + lane * 4));
                d[j][0] += v.x; d[j][1] += v.y; d[j][2] += v.z; d[j][3] += v.w;
            }
        }

        // ---- epilogue: rows wm*16+g and +8 ----
        float lsum = 0.0f, psum = 0.0f;
        #pragma unroll
        for (int half = 0; half < 2; half++) {
            const int lrow = wm * 16 + g + half * 8;
            const float xnv = xn[lrow];
            const int   tg  = tgt[r0 + lrow];
            float ap = -1e30f, an = 1e30f;
            #pragma unroll
            for (int j = 0; j < 7; j++) {
                #pragma unroll
                for (int e = 0; e < 2; e++) {
                    int n = j * 8 + 2 * q4 + e;
                    if (n >= NC || !sflags[n]) continue;
                    float S = d[j][half * 2 + e];
                    float d2 = xnv + scn[n] - 2.0f * S;
                    float dd = sqrtf(fmaxf(d2, 1e-12f));
                    if (n == tg) ap = dd;
                    else an = fminf(an, dd);
                }
            }
            #pragma unroll
            for (int o = 1; o < 4; o <<= 1) {
                ap = fmaxf(ap, __shfl_xor_sync(0xffffffffu, ap, o));
                an = fminf(an, __shfl_xor_sync(0xffffffffu, an, o));
            }
            if (q4 == 0) {
                lsum += fmaxf(ap - an + MARGINF, 0.0f);
                psum += (an > ap) ? 1.0f : 0.0f;
            }
        }
        #pragma unroll
        for (int o = 16; o; o >>= 1) {
            lsum += __shfl_xor_sync(0xffffffffu, lsum, o);
            psum += __shfl_xor_sync(0xffffffffu, psum, o);
        }
        if (lane == 0) red[wm] = make_float2(lsum, psum);
    }
    __syncthreads();

    // ---- publish partial + last-block finalize ----
    __shared__ int lastflag;
    if (tid == 0) {
        g_partial[blockIdx.x] = make_float2(red[0].x + red[1].x,
                                            red[0].y + red[1].y);
        __threadfence();
        int old = atomicAdd(&g_done, 1);
        lastflag = (old == GRID_MAIN - 1) ? 1 : 0;
    }
    __syncthreads();

    if (lastflag) {
        float2* fs = (float2*)(pool + 6144);   // finalize scratch aliases pool
        fs[tid] = g_partial[tid];
        __syncthreads();
        #pragma unroll
        for (int o = 128; o; o >>= 1) {
            if (tid < o) { fs[tid].x += fs[tid + o].x; fs[tid].y += fs[tid + o].y; }
            __syncthreads();
        }
        if (tid == 0) {
            out[0] = fs[0].x / (float)BB;
            out[1] = fs[0].y / (float)BB;
            g_done = 0;   // reset for graph replay
        }
    }
}

extern "C" void kernel_launch(void* const* d_in, const int* in_sizes, int n_in,
                              void* d_out, int out_size) {
    const float* x   = (const float*)d_in[0];
    const int*   tgt = (const int*)d_in[1];
    const float* cen = (const float*)d_in[2];
    float* out = (float*)d_out;

    tcl_mma_kernel<<<GRID_MAIN, 256>>>(x, tgt, cen, out);
}